// round 3
// baseline (speedup 1.0000x reference)
#include <cuda_runtime.h>
#include <stdint.h>

// Problem constants (fixed by the dataset)
#define DIN 128
#define H1  64
#define H2  32
#define MAXN 100352          // 98 * 1024
#define MAXE 1600000
#define NTHREADS 256
#define SCAN_B 1024

// ---------------------------------------------------------------------------
// Scratch (static device globals — no allocation allowed in kernel_launch)
// ---------------------------------------------------------------------------
__device__ float g_dinv[MAXN];
__device__ int   g_cnt [MAXN];      // in-degree (without self loop)
__device__ int   g_row [MAXN];      // CSR row start (exclusive scan of cnt)
__device__ int   g_cur [MAXN];      // fill cursor
__device__ int   g_bsum[SCAN_B];    // per-block scan totals
__device__ int   g_boff[SCAN_B];    // scanned block offsets
__device__ int   g_csr_src[MAXE];
__device__ float g_t1[MAXN * H1];   // x @ W1
__device__ float g_h1[MAXN * H1];   // relu(aggregated layer 1)
__device__ float g_t2[MAXN * H2];   // h1 @ W2

// ---------------------------------------------------------------------------
// zero counters
// ---------------------------------------------------------------------------
__global__ void k_zero(int N) {
    int i = blockIdx.x * blockDim.x + threadIdx.x;
    if (i < N) g_cnt[i] = 0;
}

// count in-degrees (edge_index is int32: row 0 = src, row 1 = dst)
__global__ void k_cnt(const int* __restrict__ ei, int E) {
    int e = blockIdx.x * blockDim.x + threadIdx.x;
    if (e >= E) return;
    int dst = ei[E + e];
    atomicAdd(&g_cnt[dst], 1);
}

__global__ void k_dinv(int N) {
    int i = blockIdx.x * blockDim.x + threadIdx.x;
    if (i < N) g_dinv[i] = rsqrtf((float)(g_cnt[i] + 1));
}

// ---------------------------------------------------------------------------
// 3-stage exclusive prefix sum over g_cnt -> g_row
// ---------------------------------------------------------------------------
__global__ __launch_bounds__(SCAN_B) void k_scan1(int N) {
    __shared__ int s[SCAN_B];
    int i = blockIdx.x * SCAN_B + threadIdx.x;
    int v = (i < N) ? g_cnt[i] : 0;
    s[threadIdx.x] = v;
    __syncthreads();
    for (int off = 1; off < SCAN_B; off <<= 1) {
        int t = (threadIdx.x >= off) ? s[threadIdx.x - off] : 0;
        __syncthreads();
        s[threadIdx.x] += t;
        __syncthreads();
    }
    if (i < N) g_row[i] = s[threadIdx.x] - v;   // exclusive
    if (threadIdx.x == SCAN_B - 1) g_bsum[blockIdx.x] = s[SCAN_B - 1];
}

__global__ __launch_bounds__(SCAN_B) void k_scan2(int nb) {
    __shared__ int s[SCAN_B];
    int v = (threadIdx.x < nb) ? g_bsum[threadIdx.x] : 0;
    s[threadIdx.x] = v;
    __syncthreads();
    for (int off = 1; off < SCAN_B; off <<= 1) {
        int t = (threadIdx.x >= off) ? s[threadIdx.x - off] : 0;
        __syncthreads();
        s[threadIdx.x] += t;
        __syncthreads();
    }
    if (threadIdx.x < nb) g_boff[threadIdx.x] = s[threadIdx.x] - v;
}

__global__ void k_scan3(int N) {
    int i = blockIdx.x * blockDim.x + threadIdx.x;
    if (i >= N) return;
    int r = g_row[i] + g_boff[i / SCAN_B];
    g_row[i] = r;
    g_cur[i] = r;
}

// fill CSR buckets (order within a bucket is arbitrary; fp-sum permutation
// differences are ~1e-7 relative, far inside the 1e-3 gate)
__global__ void k_fill(const int* __restrict__ ei, int E) {
    int e = blockIdx.x * blockDim.x + threadIdx.x;
    if (e >= E) return;
    int dst = ei[E + e];
    int pos = atomicAdd(&g_cur[dst], 1);
    g_csr_src[pos] = ei[e];
}

// ---------------------------------------------------------------------------
// GEMM1: t1 = x @ W1   (N x 128) @ (128 x 64); W1 in smem, one thread/row
// ---------------------------------------------------------------------------
__global__ __launch_bounds__(128) void k_gemm1(
    const float* __restrict__ x, const float* __restrict__ W1, int N)
{
    __shared__ float w[DIN * H1];  // 32 KB
    for (int i = threadIdx.x; i < DIN * H1; i += blockDim.x) w[i] = W1[i];
    __syncthreads();

    int row = blockIdx.x * blockDim.x + threadIdx.x;
    if (row >= N) return;

    const float4* xr = (const float4*)(x + (size_t)row * DIN);
    float acc[H1];
#pragma unroll
    for (int j = 0; j < H1; j++) acc[j] = 0.f;

#pragma unroll 1
    for (int kk = 0; kk < DIN / 4; kk++) {
        float4 xv = xr[kk];
        int kb = kk * 4;
#pragma unroll
        for (int u = 0; u < 4; u++) {
            float xs = (u == 0) ? xv.x : (u == 1) ? xv.y : (u == 2) ? xv.z : xv.w;
            const float4* wr = (const float4*)&w[(kb + u) * H1];
#pragma unroll
            for (int j = 0; j < H1 / 4; j++) {
                float4 wv = wr[j];
                acc[4 * j + 0] += xs * wv.x;
                acc[4 * j + 1] += xs * wv.y;
                acc[4 * j + 2] += xs * wv.z;
                acc[4 * j + 3] += xs * wv.w;
            }
        }
    }

    float4* out = (float4*)(g_t1 + (size_t)row * H1);
#pragma unroll
    for (int j = 0; j < H1 / 4; j++)
        out[j] = make_float4(acc[4 * j], acc[4 * j + 1], acc[4 * j + 2], acc[4 * j + 3]);
}

// ---------------------------------------------------------------------------
// Gather layer 1: h1[dst] = relu( t1[dst]*dinv^2 + sum_e t1[src]*norm )
// 16 lanes per node, one float4 per lane. No float atomics anywhere.
// ---------------------------------------------------------------------------
__global__ __launch_bounds__(NTHREADS) void k_gather1(int N) {
    int t = blockIdx.x * blockDim.x + threadIdx.x;
    int node = t >> 4;
    int lane = t & 15;
    if (node >= N) return;

    float dv = g_dinv[node];
    float d2 = dv * dv;

    float4 acc = ((const float4*)(g_t1 + (size_t)node * H1))[lane];
    acc.x *= d2; acc.y *= d2; acc.z *= d2; acc.w *= d2;

    int start = g_row[node];
    int cnt   = g_cnt[node];
    int j = 0;
#pragma unroll 1
    for (; j + 2 <= cnt; j += 2) {
        int s0 = g_csr_src[start + j];
        int s1 = g_csr_src[start + j + 1];
        float n0 = g_dinv[s0] * dv;
        float n1 = g_dinv[s1] * dv;
        float4 v0 = ((const float4*)(g_t1 + (size_t)s0 * H1))[lane];
        float4 v1 = ((const float4*)(g_t1 + (size_t)s1 * H1))[lane];
        acc.x += v0.x * n0; acc.y += v0.y * n0; acc.z += v0.z * n0; acc.w += v0.w * n0;
        acc.x += v1.x * n1; acc.y += v1.y * n1; acc.z += v1.z * n1; acc.w += v1.w * n1;
    }
    if (j < cnt) {
        int s0 = g_csr_src[start + j];
        float n0 = g_dinv[s0] * dv;
        float4 v0 = ((const float4*)(g_t1 + (size_t)s0 * H1))[lane];
        acc.x += v0.x * n0; acc.y += v0.y * n0; acc.z += v0.z * n0; acc.w += v0.w * n0;
    }
    acc.x = fmaxf(acc.x, 0.f);
    acc.y = fmaxf(acc.y, 0.f);
    acc.z = fmaxf(acc.z, 0.f);
    acc.w = fmaxf(acc.w, 0.f);
    ((float4*)(g_h1 + (size_t)node * H1))[lane] = acc;
}

// ---------------------------------------------------------------------------
// GEMM2: t2 = h1 @ W2   (N x 64) @ (64 x 32); one thread/row
// ---------------------------------------------------------------------------
__global__ __launch_bounds__(NTHREADS) void k_gemm2(
    const float* __restrict__ W2, int N)
{
    __shared__ float w[H1 * H2];  // 8 KB
    for (int i = threadIdx.x; i < H1 * H2; i += blockDim.x) w[i] = W2[i];
    __syncthreads();

    int row = blockIdx.x * blockDim.x + threadIdx.x;
    if (row >= N) return;

    const float4* hr = (const float4*)(g_h1 + (size_t)row * H1);
    float acc[H2];
#pragma unroll
    for (int j = 0; j < H2; j++) acc[j] = 0.f;

#pragma unroll 1
    for (int kk = 0; kk < H1 / 4; kk++) {
        float4 hv4 = hr[kk];
        int kb = kk * 4;
#pragma unroll
        for (int u = 0; u < 4; u++) {
            float hv = (u == 0) ? hv4.x : (u == 1) ? hv4.y : (u == 2) ? hv4.z : hv4.w;
            const float4* wr = (const float4*)&w[(kb + u) * H2];
#pragma unroll
            for (int j = 0; j < H2 / 4; j++) {
                float4 wv = wr[j];
                acc[4 * j + 0] += hv * wv.x;
                acc[4 * j + 1] += hv * wv.y;
                acc[4 * j + 2] += hv * wv.z;
                acc[4 * j + 3] += hv * wv.w;
            }
        }
    }

    float4* t2o = (float4*)(g_t2 + (size_t)row * H2);
#pragma unroll
    for (int j = 0; j < H2 / 4; j++)
        t2o[j] = make_float4(acc[4 * j], acc[4 * j + 1], acc[4 * j + 2], acc[4 * j + 3]);
}

// ---------------------------------------------------------------------------
// Gather layer 2: out[dst] = t2[dst]*dinv^2 + sum_e t2[src]*norm
// 8 lanes per node, one float4 per lane. No float atomics.
// ---------------------------------------------------------------------------
__global__ __launch_bounds__(NTHREADS) void k_gather2(float* __restrict__ out, int N) {
    int t = blockIdx.x * blockDim.x + threadIdx.x;
    int node = t >> 3;
    int lane = t & 7;
    if (node >= N) return;

    float dv = g_dinv[node];
    float d2 = dv * dv;

    float4 acc = ((const float4*)(g_t2 + (size_t)node * H2))[lane];
    acc.x *= d2; acc.y *= d2; acc.z *= d2; acc.w *= d2;

    int start = g_row[node];
    int cnt   = g_cnt[node];
    int j = 0;
#pragma unroll 1
    for (; j + 2 <= cnt; j += 2) {
        int s0 = g_csr_src[start + j];
        int s1 = g_csr_src[start + j + 1];
        float n0 = g_dinv[s0] * dv;
        float n1 = g_dinv[s1] * dv;
        float4 v0 = ((const float4*)(g_t2 + (size_t)s0 * H2))[lane];
        float4 v1 = ((const float4*)(g_t2 + (size_t)s1 * H2))[lane];
        acc.x += v0.x * n0; acc.y += v0.y * n0; acc.z += v0.z * n0; acc.w += v0.w * n0;
        acc.x += v1.x * n1; acc.y += v1.y * n1; acc.z += v1.z * n1; acc.w += v1.w * n1;
    }
    if (j < cnt) {
        int s0 = g_csr_src[start + j];
        float n0 = g_dinv[s0] * dv;
        float4 v0 = ((const float4*)(g_t2 + (size_t)s0 * H2))[lane];
        acc.x += v0.x * n0; acc.y += v0.y * n0; acc.z += v0.z * n0; acc.w += v0.w * n0;
    }
    ((float4*)(out + (size_t)node * H2))[lane] = acc;
}

// ---------------------------------------------------------------------------
// Launch
// Inputs: d_in[0]=x [N,128] f32, d_in[1]=edge_index [2,E] int32,
//         d_in[2]=W1 [128,64] f32, d_in[3]=W2 [64,32] f32
// Output: z [N,32] f32
// ---------------------------------------------------------------------------
extern "C" void kernel_launch(void* const* d_in, const int* in_sizes, int n_in,
                              void* d_out, int out_size)
{
    const float* x  = (const float*)d_in[0];
    const int*   ei = (const int*)d_in[1];
    const float* W1 = (const float*)d_in[2];
    const float* W2 = (const float*)d_in[3];
    float*       out = (float*)d_out;

    int N = in_sizes[0] / DIN;
    int E = in_sizes[1] / 2;
    int nb = (N + SCAN_B - 1) / SCAN_B;

    k_zero<<<(N + NTHREADS - 1) / NTHREADS, NTHREADS>>>(N);
    k_cnt <<<(E + NTHREADS - 1) / NTHREADS, NTHREADS>>>(ei, E);
    k_dinv<<<(N + NTHREADS - 1) / NTHREADS, NTHREADS>>>(N);

    k_scan1<<<nb, SCAN_B>>>(N);
    k_scan2<<<1, SCAN_B>>>(nb);
    k_scan3<<<(N + NTHREADS - 1) / NTHREADS, NTHREADS>>>(N);
    k_fill <<<(E + NTHREADS - 1) / NTHREADS, NTHREADS>>>(ei, E);

    k_gemm1<<<(N + 127) / 128, 128>>>(x, W1, N);

    {
        long long th = (long long)N * 16;
        k_gather1<<<(int)((th + NTHREADS - 1) / NTHREADS), NTHREADS>>>(N);
    }

    k_gemm2<<<(N + NTHREADS - 1) / NTHREADS, NTHREADS>>>(W2, N);

    {
        long long th = (long long)N * 8;
        k_gather2<<<(int)((th + NTHREADS - 1) / NTHREADS), NTHREADS>>>(out, N);
    }
}

// round 5
// speedup vs baseline: 1.0590x; 1.0590x over previous
#include <cuda_runtime.h>
#include <cuda_fp16.h>
#include <stdint.h>

// Problem constants (fixed by the dataset)
#define DIN 128
#define H1  64
#define H2  32
#define MAXN 100352          // 98 * 1024
#define MAXE 1600000
#define NTHREADS 256
#define SCAN_B 1024

// ---------------------------------------------------------------------------
// Scratch (static device globals — no allocation allowed in kernel_launch)
// ---------------------------------------------------------------------------
__device__ float      g_dinv[MAXN];
__device__ int        g_cnt [MAXN];          // in-degree (without self loop)
__device__ int        g_row [MAXN];          // CSR row start
__device__ int        g_cur [MAXN];          // fill cursor
__device__ int        g_bsum[SCAN_B];        // per-block scan totals
__device__ int        g_boff[SCAN_B];        // scanned block offsets
__device__ unsigned long long g_csr[MAXE];   // packed {src:int32, norm:f32}
__device__ __half     g_t1h[MAXN * H1];      // x @ W1 (fp16)
__device__ float      g_h1 [MAXN * H1];      // relu(aggregated layer 1) fp32
__device__ __half     g_t2h[MAXN * H2];      // h1 @ W2 (fp16)

// ---------------------------------------------------------------------------
// bit-cast helpers (the intrinsics __half2_as_uint etc. don't exist)
// ---------------------------------------------------------------------------
__device__ __forceinline__ unsigned h2_to_u(__half2 h) {
    union { __half2 h; unsigned u; } c; c.h = h; return c.u;
}
__device__ __forceinline__ __half2 u_to_h2(unsigned u) {
    union { unsigned u; __half2 h; } c; c.u = u; return c.h;
}

// ---------------------------------------------------------------------------
// packed fp32x2 FMA (Blackwell-only PTX form; 2x FFMA throughput)
// ---------------------------------------------------------------------------
__device__ __forceinline__ unsigned long long fma2(
    unsigned long long a, unsigned long long b, unsigned long long c)
{
    unsigned long long d;
    asm("fma.rn.f32x2 %0, %1, %2, %3;" : "=l"(d) : "l"(a), "l"(b), "l"(c));
    return d;
}
__device__ __forceinline__ unsigned long long pack2(float s) {
    unsigned long long d;
    asm("mov.b64 %0, {%1, %1};" : "=l"(d) : "f"(s));
    return d;
}

// ---------------------------------------------------------------------------
// preprocessing
// ---------------------------------------------------------------------------
__global__ void k_zero(int N) {
    int i = blockIdx.x * blockDim.x + threadIdx.x;
    if (i < N) g_cnt[i] = 0;
}

__global__ void k_cnt(const int* __restrict__ ei, int E) {
    int e = blockIdx.x * blockDim.x + threadIdx.x;
    if (e >= E) return;
    atomicAdd(&g_cnt[ei[E + e]], 1);
}

// block-level exclusive scan (warp shuffles)
__global__ __launch_bounds__(SCAN_B) void k_scan1(int N) {
    int lane = threadIdx.x & 31, warp = threadIdx.x >> 5;
    int i = blockIdx.x * SCAN_B + threadIdx.x;
    int v = (i < N) ? g_cnt[i] : 0;
    int x = v;
#pragma unroll
    for (int off = 1; off < 32; off <<= 1) {
        int t = __shfl_up_sync(0xffffffff, x, off);
        if (lane >= off) x += t;
    }
    __shared__ int wt[32];
    if (lane == 31) wt[warp] = x;
    __syncthreads();
    if (warp == 0) {
        int y = wt[lane];
        int z = y;
#pragma unroll
        for (int off = 1; off < 32; off <<= 1) {
            int t = __shfl_up_sync(0xffffffff, z, off);
            if (lane >= off) z += t;
        }
        wt[lane] = z - y;   // exclusive offsets
    }
    __syncthreads();
    int base = wt[warp];
    if (i < N) g_row[i] = base + x - v;   // exclusive
    if (threadIdx.x == SCAN_B - 1) g_bsum[blockIdx.x] = base + x;
}

// scan the <=128 block totals
__global__ __launch_bounds__(128) void k_scan2(int nb) {
    int lane = threadIdx.x & 31, warp = threadIdx.x >> 5;
    int v = (threadIdx.x < nb) ? g_bsum[threadIdx.x] : 0;
    int x = v;
#pragma unroll
    for (int off = 1; off < 32; off <<= 1) {
        int t = __shfl_up_sync(0xffffffff, x, off);
        if (lane >= off) x += t;
    }
    __shared__ int wt[4];
    if (lane == 31) wt[warp] = x;
    __syncthreads();
    int base = 0;
    for (int k = 0; k < warp; k++) base += wt[k];
    if (threadIdx.x < nb) g_boff[threadIdx.x] = base + x - v;
}

// finalize row offsets, cursors, and dinv
__global__ void k_scan3(int N) {
    int i = blockIdx.x * blockDim.x + threadIdx.x;
    if (i >= N) return;
    int r = g_row[i] + g_boff[i >> 10];
    g_row[i] = r;
    g_cur[i] = r;
    g_dinv[i] = rsqrtf((float)(g_cnt[i] + 1));
}

// fill CSR buckets with packed {src, norm}
__global__ void k_fill(const int* __restrict__ ei, int E) {
    int e = blockIdx.x * blockDim.x + threadIdx.x;
    if (e >= E) return;
    int src = ei[e];
    int dst = ei[E + e];
    float norm = g_dinv[src] * g_dinv[dst];
    int pos = atomicAdd(&g_cur[dst], 1);
    g_csr[pos] = (unsigned long long)(unsigned)src |
                 ((unsigned long long)__float_as_uint(norm) << 32);
}

// ---------------------------------------------------------------------------
// GEMM1: t1 = x @ W1 (N x 128)@(128 x 64), packed f32x2 FMA, fp16 output
// ---------------------------------------------------------------------------
__global__ __launch_bounds__(128) void k_gemm1(
    const float* __restrict__ x, const float* __restrict__ W1, int N)
{
    __shared__ float w[DIN * H1];  // 32 KB
    for (int i = threadIdx.x; i < DIN * H1; i += blockDim.x) w[i] = W1[i];
    __syncthreads();

    int row = blockIdx.x * blockDim.x + threadIdx.x;
    if (row >= N) return;

    const float4* xr = (const float4*)(x + (size_t)row * DIN);
    unsigned long long acc[H1 / 2];
#pragma unroll
    for (int j = 0; j < H1 / 2; j++) acc[j] = 0ull;

#pragma unroll 1
    for (int kk = 0; kk < DIN / 4; kk++) {
        float4 xv = xr[kk];
        int kb = kk * 4;
#pragma unroll
        for (int u = 0; u < 4; u++) {
            float xs = (u == 0) ? xv.x : (u == 1) ? xv.y : (u == 2) ? xv.z : xv.w;
            unsigned long long xx = pack2(xs);
            const ulonglong2* wr = (const ulonglong2*)&w[(kb + u) * H1];
#pragma unroll
            for (int j = 0; j < H1 / 4; j++) {
                ulonglong2 wv = wr[j];
                acc[2 * j + 0] = fma2(xx, wv.x, acc[2 * j + 0]);
                acc[2 * j + 1] = fma2(xx, wv.y, acc[2 * j + 1]);
            }
        }
    }

    // convert 32 float2 -> 32 half2 and store 128 B
    uint4* out = (uint4*)(g_t1h + (size_t)row * H1);
#pragma unroll
    for (int q = 0; q < 8; q++) {
        uint4 o;
        float2 f0 = *(float2*)&acc[4 * q + 0];
        float2 f1 = *(float2*)&acc[4 * q + 1];
        float2 f2 = *(float2*)&acc[4 * q + 2];
        float2 f3 = *(float2*)&acc[4 * q + 3];
        o.x = h2_to_u(__float22half2_rn(f0));
        o.y = h2_to_u(__float22half2_rn(f1));
        o.z = h2_to_u(__float22half2_rn(f2));
        o.w = h2_to_u(__float22half2_rn(f3));
        out[q] = o;
    }
}

// ---------------------------------------------------------------------------
// Gather layer 1: h1[dst] = relu( t1[dst]*dinv^2 + sum_e t1[src]*norm )
// 8 lanes per node, each lane owns 8 halves (16 B). No float atomics.
// ---------------------------------------------------------------------------
__device__ __forceinline__ void acc_h8(float2 a[4], uint4 v, float n) {
    float2 f;
    f = __half22float2(u_to_h2(v.x)); a[0].x += f.x * n; a[0].y += f.y * n;
    f = __half22float2(u_to_h2(v.y)); a[1].x += f.x * n; a[1].y += f.y * n;
    f = __half22float2(u_to_h2(v.z)); a[2].x += f.x * n; a[2].y += f.y * n;
    f = __half22float2(u_to_h2(v.w)); a[3].x += f.x * n; a[3].y += f.y * n;
}

__global__ __launch_bounds__(NTHREADS) void k_gather1(int N) {
    int t = blockIdx.x * blockDim.x + threadIdx.x;
    int node = t >> 3;
    int lane = t & 7;
    if (node >= N) return;

    float dv = g_dinv[node];
    float d2 = dv * dv;

    float2 a[4] = {{0,0},{0,0},{0,0},{0,0}};
    acc_h8(a, ((const uint4*)(g_t1h + (size_t)node * H1))[lane], d2);

    int start = g_row[node];
    int cnt   = g_cnt[node];
    int j = 0;
#pragma unroll 1
    for (; j + 2 <= cnt; j += 2) {
        unsigned long long p0 = g_csr[start + j];
        unsigned long long p1 = g_csr[start + j + 1];
        int   s0 = (int)(unsigned)p0;
        int   s1 = (int)(unsigned)p1;
        float n0 = __uint_as_float((unsigned)(p0 >> 32));
        float n1 = __uint_as_float((unsigned)(p1 >> 32));
        uint4 v0 = ((const uint4*)(g_t1h + (size_t)s0 * H1))[lane];
        uint4 v1 = ((const uint4*)(g_t1h + (size_t)s1 * H1))[lane];
        acc_h8(a, v0, n0);
        acc_h8(a, v1, n1);
    }
    if (j < cnt) {
        unsigned long long p0 = g_csr[start + j];
        int   s0 = (int)(unsigned)p0;
        float n0 = __uint_as_float((unsigned)(p0 >> 32));
        acc_h8(a, ((const uint4*)(g_t1h + (size_t)s0 * H1))[lane], n0);
    }

    float4* out = (float4*)(g_h1 + (size_t)node * H1 + lane * 8);
    out[0] = make_float4(fmaxf(a[0].x, 0.f), fmaxf(a[0].y, 0.f),
                         fmaxf(a[1].x, 0.f), fmaxf(a[1].y, 0.f));
    out[1] = make_float4(fmaxf(a[2].x, 0.f), fmaxf(a[2].y, 0.f),
                         fmaxf(a[3].x, 0.f), fmaxf(a[3].y, 0.f));
}

// ---------------------------------------------------------------------------
// GEMM2: t2 = h1 @ W2 (N x 64)@(64 x 32), packed f32x2 FMA, fp16 output
// ---------------------------------------------------------------------------
__global__ __launch_bounds__(NTHREADS) void k_gemm2(
    const float* __restrict__ W2, int N)
{
    __shared__ float w[H1 * H2];  // 8 KB
    for (int i = threadIdx.x; i < H1 * H2; i += blockDim.x) w[i] = W2[i];
    __syncthreads();

    int row = blockIdx.x * blockDim.x + threadIdx.x;
    if (row >= N) return;

    const float4* hr = (const float4*)(g_h1 + (size_t)row * H1);
    unsigned long long acc[H2 / 2];
#pragma unroll
    for (int j = 0; j < H2 / 2; j++) acc[j] = 0ull;

#pragma unroll 1
    for (int kk = 0; kk < H1 / 4; kk++) {
        float4 hv4 = hr[kk];
        int kb = kk * 4;
#pragma unroll
        for (int u = 0; u < 4; u++) {
            float hv = (u == 0) ? hv4.x : (u == 1) ? hv4.y : (u == 2) ? hv4.z : hv4.w;
            unsigned long long hh = pack2(hv);
            const ulonglong2* wr = (const ulonglong2*)&w[(kb + u) * H2];
#pragma unroll
            for (int j = 0; j < H2 / 4; j++) {
                ulonglong2 wv = wr[j];
                acc[2 * j + 0] = fma2(hh, wv.x, acc[2 * j + 0]);
                acc[2 * j + 1] = fma2(hh, wv.y, acc[2 * j + 1]);
            }
        }
    }

    uint4* out = (uint4*)(g_t2h + (size_t)row * H2);
#pragma unroll
    for (int q = 0; q < 4; q++) {
        uint4 o;
        float2 f0 = *(float2*)&acc[4 * q + 0];
        float2 f1 = *(float2*)&acc[4 * q + 1];
        float2 f2 = *(float2*)&acc[4 * q + 2];
        float2 f3 = *(float2*)&acc[4 * q + 3];
        o.x = h2_to_u(__float22half2_rn(f0));
        o.y = h2_to_u(__float22half2_rn(f1));
        o.z = h2_to_u(__float22half2_rn(f2));
        o.w = h2_to_u(__float22half2_rn(f3));
        out[q] = o;
    }
}

// ---------------------------------------------------------------------------
// Gather layer 2: out[dst] = t2[dst]*dinv^2 + sum_e t2[src]*norm
// 4 lanes per node, each lane owns 8 halves. fp32 output.
// ---------------------------------------------------------------------------
__global__ __launch_bounds__(NTHREADS) void k_gather2(float* __restrict__ out, int N) {
    int t = blockIdx.x * blockDim.x + threadIdx.x;
    int node = t >> 2;
    int lane = t & 3;
    if (node >= N) return;

    float dv = g_dinv[node];
    float d2 = dv * dv;

    float2 a[4] = {{0,0},{0,0},{0,0},{0,0}};
    acc_h8(a, ((const uint4*)(g_t2h + (size_t)node * H2))[lane], d2);

    int start = g_row[node];
    int cnt   = g_cnt[node];
    int j = 0;
#pragma unroll 1
    for (; j + 2 <= cnt; j += 2) {
        unsigned long long p0 = g_csr[start + j];
        unsigned long long p1 = g_csr[start + j + 1];
        int   s0 = (int)(unsigned)p0;
        int   s1 = (int)(unsigned)p1;
        float n0 = __uint_as_float((unsigned)(p0 >> 32));
        float n1 = __uint_as_float((unsigned)(p1 >> 32));
        uint4 v0 = ((const uint4*)(g_t2h + (size_t)s0 * H2))[lane];
        uint4 v1 = ((const uint4*)(g_t2h + (size_t)s1 * H2))[lane];
        acc_h8(a, v0, n0);
        acc_h8(a, v1, n1);
    }
    if (j < cnt) {
        unsigned long long p0 = g_csr[start + j];
        int   s0 = (int)(unsigned)p0;
        float n0 = __uint_as_float((unsigned)(p0 >> 32));
        acc_h8(a, ((const uint4*)(g_t2h + (size_t)s0 * H2))[lane], n0);
    }

    float4* o = (float4*)(out + (size_t)node * H2 + lane * 8);
    o[0] = make_float4(a[0].x, a[0].y, a[1].x, a[1].y);
    o[1] = make_float4(a[2].x, a[2].y, a[3].x, a[3].y);
}

// ---------------------------------------------------------------------------
// Launch
// Inputs: d_in[0]=x [N,128] f32, d_in[1]=edge_index [2,E] int32,
//         d_in[2]=W1 [128,64] f32, d_in[3]=W2 [64,32] f32
// Output: z [N,32] f32
// ---------------------------------------------------------------------------
extern "C" void kernel_launch(void* const* d_in, const int* in_sizes, int n_in,
                              void* d_out, int out_size)
{
    const float* x  = (const float*)d_in[0];
    const int*   ei = (const int*)d_in[1];
    const float* W1 = (const float*)d_in[2];
    const float* W2 = (const float*)d_in[3];
    float*       out = (float*)d_out;

    int N = in_sizes[0] / DIN;
    int E = in_sizes[1] / 2;
    int nb = (N + SCAN_B - 1) / SCAN_B;

    k_zero <<<(N + NTHREADS - 1) / NTHREADS, NTHREADS>>>(N);
    k_cnt  <<<(E + NTHREADS - 1) / NTHREADS, NTHREADS>>>(ei, E);
    k_scan1<<<nb, SCAN_B>>>(N);
    k_scan2<<<1, 128>>>(nb);
    k_scan3<<<(N + NTHREADS - 1) / NTHREADS, NTHREADS>>>(N);
    k_fill <<<(E + NTHREADS - 1) / NTHREADS, NTHREADS>>>(ei, E);

    k_gemm1<<<(N + 127) / 128, 128>>>(x, W1, N);

    {
        long long th = (long long)N * 8;
        k_gather1<<<(int)((th + NTHREADS - 1) / NTHREADS), NTHREADS>>>(N);
    }

    k_gemm2<<<(N + NTHREADS - 1) / NTHREADS, NTHREADS>>>(W2, N);

    {
        long long th = (long long)N * 4;
        k_gather2<<<(int)((th + NTHREADS - 1) / NTHREADS), NTHREADS>>>(out, N);
    }
}